// round 1
// baseline (speedup 1.0000x reference)
#include <cuda_runtime.h>

#define SEQ 2048
#define DIM 128
#define BHN 32
#define NROWS (BHN * SEQ)   // 65536 rows each for q and k

// Scratch: reciprocal L2 norms (no device allocation allowed -> __device__ globals)
__device__ float g_rq[NROWS];
__device__ float g_rk[NROWS];

// ---------------------------------------------------------------------------
// Kernel 1: per-row 1/max(||x||, 1e-12). One warp per row.
// ---------------------------------------------------------------------------
__global__ void norm_kernel(const float* __restrict__ q, const float* __restrict__ k) {
    int gwarp = (blockIdx.x * blockDim.x + threadIdx.x) >> 5;
    int lane = threadIdx.x & 31;
    bool is_q = gwarp < NROWS;
    int row = is_q ? gwarp : gwarp - NROWS;
    const float* src = is_q ? q : k;
    float4 v = reinterpret_cast<const float4*>(src + (size_t)row * DIM)[lane];
    float ss = v.x * v.x + v.y * v.y + v.z * v.z + v.w * v.w;
#pragma unroll
    for (int o = 16; o > 0; o >>= 1) ss += __shfl_xor_sync(0xffffffffu, ss, o);
    if (lane == 0) {
        float r = 1.0f / fmaxf(sqrtf(ss), 1e-12f);
        if (is_q) g_rq[row] = r; else g_rk[row] = r;
    }
}

// ---------------------------------------------------------------------------
// tf32 helpers
// ---------------------------------------------------------------------------
__device__ __forceinline__ float f2tf32(float x) {
    unsigned r;
    asm("cvt.rna.tf32.f32 %0, %1;" : "=r"(r) : "f"(x));
    return __uint_as_float(r);
}

__device__ __forceinline__ void mma_tf32(float c[4], const unsigned a[4], const unsigned b[2]) {
    asm volatile(
        "mma.sync.aligned.m16n8k8.row.col.f32.tf32.tf32.f32 "
        "{%0,%1,%2,%3}, {%4,%5,%6,%7}, {%8,%9}, {%0,%1,%2,%3};\n"
        : "+f"(c[0]), "+f"(c[1]), "+f"(c[2]), "+f"(c[3])
        : "r"(a[0]), "r"(a[1]), "r"(a[2]), "r"(a[3]), "r"(b[0]), "r"(b[1]));
}

// ---------------------------------------------------------------------------
// Kernel 2: per (b,h): C = Q * K^T on 128x128 tiles, epilogue
//   s = clamp(dot * rq[m] * rk[n] / temp, -100, 100); out = exp(s) + 1e-6
// Whole K=128 depth staged in shared once (no k-loop reload).
// Shared: A[128][132] + B[128][132] fp32 = 135168 bytes.
// ---------------------------------------------------------------------------
#define LDA 132
#define SMEM_BYTES (2 * 128 * LDA * 4)

__global__ __launch_bounds__(256) void gemm_exp_kernel(
    const float* __restrict__ q, const float* __restrict__ k,
    const float* __restrict__ logt, float* __restrict__ out)
{
    extern __shared__ float sm[];
    float* As = sm;
    float* Bs = sm + 128 * LDA;

    int bh = blockIdx.z;
    int bm = blockIdx.y, bn = blockIdx.x;
    int tid = threadIdx.x;
    int warp = tid >> 5, lane = tid & 31;
    int gid = lane >> 2, tig = lane & 3;     // group-of-4 row, thread-in-group
    int wm = warp >> 2, wn = warp & 3;       // 2 x 4 warp grid
    int wmo = wm * 64, wno = wn * 32;        // warp tile 64 x 32

    const float* qbase = q + ((size_t)bh * SEQ + (size_t)bm * 128) * DIM;
    const float* kbase = k + ((size_t)bh * SEQ + (size_t)bn * 128) * DIM;

    // Stage tiles to shared, converting to tf32 once at store time.
#pragma unroll
    for (int i = 0; i < 16; i++) {
        int idx = tid + i * 256;     // float4 index 0..4095
        int row = idx >> 5;
        int c4 = idx & 31;
        float4 a = reinterpret_cast<const float4*>(qbase)[(size_t)row * 32 + c4];
        float4 b = reinterpret_cast<const float4*>(kbase)[(size_t)row * 32 + c4];
        a.x = f2tf32(a.x); a.y = f2tf32(a.y); a.z = f2tf32(a.z); a.w = f2tf32(a.w);
        b.x = f2tf32(b.x); b.y = f2tf32(b.y); b.z = f2tf32(b.z); b.w = f2tf32(b.w);
        *reinterpret_cast<float4*>(&As[row * LDA + c4 * 4]) = a;
        *reinterpret_cast<float4*>(&Bs[row * LDA + c4 * 4]) = b;
    }
    __syncthreads();

    float acc[4][4][4];
#pragma unroll
    for (int mi = 0; mi < 4; mi++)
#pragma unroll
        for (int ni = 0; ni < 4; ni++)
#pragma unroll
            for (int r = 0; r < 4; r++) acc[mi][ni][r] = 0.0f;

#pragma unroll
    for (int k0 = 0; k0 < 128; k0 += 8) {
        unsigned a[4][4], b[4][2];
#pragma unroll
        for (int mi = 0; mi < 4; mi++) {
            int r = wmo + mi * 16 + gid;
            a[mi][0] = __float_as_uint(As[r * LDA + k0 + tig]);
            a[mi][1] = __float_as_uint(As[(r + 8) * LDA + k0 + tig]);
            a[mi][2] = __float_as_uint(As[r * LDA + k0 + tig + 4]);
            a[mi][3] = __float_as_uint(As[(r + 8) * LDA + k0 + tig + 4]);
        }
#pragma unroll
        for (int ni = 0; ni < 4; ni++) {
            int c = wno + ni * 8 + gid;
            b[ni][0] = __float_as_uint(Bs[c * LDA + k0 + tig]);
            b[ni][1] = __float_as_uint(Bs[c * LDA + k0 + tig + 4]);
        }
#pragma unroll
        for (int mi = 0; mi < 4; mi++)
#pragma unroll
            for (int ni = 0; ni < 4; ni++)
                mma_tf32(acc[mi][ni], a[mi], b[ni]);
    }

    // Epilogue
    float lt = *logt;
    float temp = fminf(fmaxf(__expf(lt), 0.05f), 100.0f);
    float invt = 1.0f / temp;

    int rowbase = bm * 128 + wmo;
    int colbase = bn * 128 + wno;
    const float* rqp = g_rq + (size_t)bh * SEQ;
    const float* rkp = g_rk + (size_t)bh * SEQ;

    float rk0v[4], rk1v[4];
#pragma unroll
    for (int ni = 0; ni < 4; ni++) {
        int c0 = colbase + ni * 8 + tig * 2;
        rk0v[ni] = rkp[c0];
        rk1v[ni] = rkp[c0 + 1];
    }

    size_t obase = (size_t)bh * SEQ * SEQ;
#pragma unroll
    for (int mi = 0; mi < 4; mi++) {
        int r0 = rowbase + mi * 16 + gid;
        float rq0 = rqp[r0];
        float rq1 = rqp[r0 + 8];
#pragma unroll
        for (int ni = 0; ni < 4; ni++) {
            int c0 = colbase + ni * 8 + tig * 2;
            float s00 = fminf(fmaxf(acc[mi][ni][0] * rq0 * rk0v[ni] * invt, -100.0f), 100.0f);
            float s01 = fminf(fmaxf(acc[mi][ni][1] * rq0 * rk1v[ni] * invt, -100.0f), 100.0f);
            float s10 = fminf(fmaxf(acc[mi][ni][2] * rq1 * rk0v[ni] * invt, -100.0f), 100.0f);
            float s11 = fminf(fmaxf(acc[mi][ni][3] * rq1 * rk1v[ni] * invt, -100.0f), 100.0f);
            float2 o0, o1;
            o0.x = __expf(s00) + 1e-6f;
            o0.y = __expf(s01) + 1e-6f;
            o1.x = __expf(s10) + 1e-6f;
            o1.y = __expf(s11) + 1e-6f;
            *reinterpret_cast<float2*>(&out[obase + (size_t)r0 * SEQ + c0]) = o0;
            *reinterpret_cast<float2*>(&out[obase + (size_t)(r0 + 8) * SEQ + c0]) = o1;
        }
    }
}

// ---------------------------------------------------------------------------
// Launcher (graph-capturable: kernel launches only)
// ---------------------------------------------------------------------------
extern "C" void kernel_launch(void* const* d_in, const int* in_sizes, int n_in,
                              void* d_out, int out_size) {
    const float* q  = (const float*)d_in[0];
    const float* k  = (const float*)d_in[1];
    const float* lt = (const float*)d_in[2];
    float* out = (float*)d_out;

    // 2 * 65536 rows, 1 warp/row, 8 warps/block
    norm_kernel<<<(2 * NROWS) / 8, 256>>>(q, k);

    cudaFuncSetAttribute(gemm_exp_kernel,
                         cudaFuncAttributeMaxDynamicSharedMemorySize, SMEM_BYTES);
    dim3 grid(16, 16, 32);  // (bn, bm, bh)
    gemm_exp_kernel<<<grid, 256, SMEM_BYTES>>>(q, k, lt, out);
}

// round 2
// speedup vs baseline: 1.0050x; 1.0050x over previous
#include <cuda_runtime.h>

#define SEQ 2048
#define DIM 128
#define BHN 32
#define NROWS (BHN * SEQ)   // 65536 rows each for q and k

// Scratch: reciprocal L2 norms (no device allocation allowed -> __device__ globals)
__device__ float g_rq[NROWS];
__device__ float g_rk[NROWS];

// ---------------------------------------------------------------------------
// Kernel 1: per-row 1/max(||x||, 1e-12). One warp per row.
// ---------------------------------------------------------------------------
__global__ void norm_kernel(const float* __restrict__ q, const float* __restrict__ k) {
    int gwarp = (blockIdx.x * blockDim.x + threadIdx.x) >> 5;
    int lane = threadIdx.x & 31;
    bool is_q = gwarp < NROWS;
    int row = is_q ? gwarp : gwarp - NROWS;
    const float* src = is_q ? q : k;
    float4 v = reinterpret_cast<const float4*>(src + (size_t)row * DIM)[lane];
    float ss = v.x * v.x + v.y * v.y + v.z * v.z + v.w * v.w;
#pragma unroll
    for (int o = 16; o > 0; o >>= 1) ss += __shfl_xor_sync(0xffffffffu, ss, o);
    if (lane == 0) {
        float r = 1.0f / fmaxf(sqrtf(ss), 1e-12f);
        if (is_q) g_rq[row] = r; else g_rk[row] = r;
    }
}

// ---------------------------------------------------------------------------
// tf32 helpers
// ---------------------------------------------------------------------------
__device__ __forceinline__ float f2tf32(float x) {
    unsigned r;
    asm("cvt.rna.tf32.f32 %0, %1;" : "=r"(r) : "f"(x));
    return __uint_as_float(r);
}

__device__ __forceinline__ void mma_tf32(float c[4], const unsigned a[4], const unsigned b[2]) {
    asm volatile(
        "mma.sync.aligned.m16n8k8.row.col.f32.tf32.tf32.f32 "
        "{%0,%1,%2,%3}, {%4,%5,%6,%7}, {%8,%9}, {%0,%1,%2,%3};\n"
        : "+f"(c[0]), "+f"(c[1]), "+f"(c[2]), "+f"(c[3])
        : "r"(a[0]), "r"(a[1]), "r"(a[2]), "r"(a[3]), "r"(b[0]), "r"(b[1]));
}

// ---------------------------------------------------------------------------
// Kernel 2: per (b,h): C = Q * K^T on 128x128 tiles, epilogue
//   s = clamp(dot * rq[m] * rk[n] / temp, -100, 100); out = exp(s) + 1e-6
// Whole K=128 depth staged in shared once (no k-loop reload).
// Shared: A[128][132] + B[128][132] fp32 = 135168 bytes.
// ---------------------------------------------------------------------------
#define LDA 132
#define SMEM_BYTES (2 * 128 * LDA * 4)

__global__ __launch_bounds__(256) void gemm_exp_kernel(
    const float* __restrict__ q, const float* __restrict__ k,
    const float* __restrict__ logt, float* __restrict__ out)
{
    extern __shared__ float sm[];
    float* As = sm;
    float* Bs = sm + 128 * LDA;

    int bh = blockIdx.z;
    int bm = blockIdx.y, bn = blockIdx.x;
    int tid = threadIdx.x;
    int warp = tid >> 5, lane = tid & 31;
    int gid = lane >> 2, tig = lane & 3;     // group-of-4 row, thread-in-group
    int wm = warp >> 2, wn = warp & 3;       // 2 x 4 warp grid
    int wmo = wm * 64, wno = wn * 32;        // warp tile 64 x 32

    const float* qbase = q + ((size_t)bh * SEQ + (size_t)bm * 128) * DIM;
    const float* kbase = k + ((size_t)bh * SEQ + (size_t)bn * 128) * DIM;

    // Stage tiles to shared, converting to tf32 once at store time.
#pragma unroll
    for (int i = 0; i < 16; i++) {
        int idx = tid + i * 256;     // float4 index 0..4095
        int row = idx >> 5;
        int c4 = idx & 31;
        float4 a = reinterpret_cast<const float4*>(qbase)[(size_t)row * 32 + c4];
        float4 b = reinterpret_cast<const float4*>(kbase)[(size_t)row * 32 + c4];
        a.x = f2tf32(a.x); a.y = f2tf32(a.y); a.z = f2tf32(a.z); a.w = f2tf32(a.w);
        b.x = f2tf32(b.x); b.y = f2tf32(b.y); b.z = f2tf32(b.z); b.w = f2tf32(b.w);
        *reinterpret_cast<float4*>(&As[row * LDA + c4 * 4]) = a;
        *reinterpret_cast<float4*>(&Bs[row * LDA + c4 * 4]) = b;
    }
    __syncthreads();

    float acc[4][4][4];
#pragma unroll
    for (int mi = 0; mi < 4; mi++)
#pragma unroll
        for (int ni = 0; ni < 4; ni++)
#pragma unroll
            for (int r = 0; r < 4; r++) acc[mi][ni][r] = 0.0f;

#pragma unroll
    for (int k0 = 0; k0 < 128; k0 += 8) {
        unsigned a[4][4], b[4][2];
#pragma unroll
        for (int mi = 0; mi < 4; mi++) {
            int r = wmo + mi * 16 + gid;
            a[mi][0] = __float_as_uint(As[r * LDA + k0 + tig]);
            a[mi][1] = __float_as_uint(As[(r + 8) * LDA + k0 + tig]);
            a[mi][2] = __float_as_uint(As[r * LDA + k0 + tig + 4]);
            a[mi][3] = __float_as_uint(As[(r + 8) * LDA + k0 + tig + 4]);
        }
#pragma unroll
        for (int ni = 0; ni < 4; ni++) {
            int c = wno + ni * 8 + gid;
            b[ni][0] = __float_as_uint(Bs[c * LDA + k0 + tig]);
            b[ni][1] = __float_as_uint(Bs[c * LDA + k0 + tig + 4]);
        }
#pragma unroll
        for (int mi = 0; mi < 4; mi++)
#pragma unroll
            for (int ni = 0; ni < 4; ni++)
                mma_tf32(acc[mi][ni], a[mi], b[ni]);
    }

    // Epilogue
    float lt = *logt;
    float temp = fminf(fmaxf(__expf(lt), 0.05f), 100.0f);
    float invt = 1.0f / temp;

    int rowbase = bm * 128 + wmo;
    int colbase = bn * 128 + wno;
    const float* rqp = g_rq + (size_t)bh * SEQ;
    const float* rkp = g_rk + (size_t)bh * SEQ;

    float rk0v[4], rk1v[4];
#pragma unroll
    for (int ni = 0; ni < 4; ni++) {
        int c0 = colbase + ni * 8 + tig * 2;
        rk0v[ni] = rkp[c0];
        rk1v[ni] = rkp[c0 + 1];
    }

    size_t obase = (size_t)bh * SEQ * SEQ;
#pragma unroll
    for (int mi = 0; mi < 4; mi++) {
        int r0 = rowbase + mi * 16 + gid;
        float rq0 = rqp[r0];
        float rq1 = rqp[r0 + 8];
#pragma unroll
        for (int ni = 0; ni < 4; ni++) {
            int c0 = colbase + ni * 8 + tig * 2;
            float s00 = fminf(fmaxf(acc[mi][ni][0] * rq0 * rk0v[ni] * invt, -100.0f), 100.0f);
            float s01 = fminf(fmaxf(acc[mi][ni][1] * rq0 * rk1v[ni] * invt, -100.0f), 100.0f);
            float s10 = fminf(fmaxf(acc[mi][ni][2] * rq1 * rk0v[ni] * invt, -100.0f), 100.0f);
            float s11 = fminf(fmaxf(acc[mi][ni][3] * rq1 * rk1v[ni] * invt, -100.0f), 100.0f);
            float2 o0, o1;
            o0.x = __expf(s00) + 1e-6f;
            o0.y = __expf(s01) + 1e-6f;
            o1.x = __expf(s10) + 1e-6f;
            o1.y = __expf(s11) + 1e-6f;
            *reinterpret_cast<float2*>(&out[obase + (size_t)r0 * SEQ + c0]) = o0;
            *reinterpret_cast<float2*>(&out[obase + (size_t)(r0 + 8) * SEQ + c0]) = o1;
        }
    }
}

// ---------------------------------------------------------------------------
// Launcher (graph-capturable: kernel launches only)
// ---------------------------------------------------------------------------
extern "C" void kernel_launch(void* const* d_in, const int* in_sizes, int n_in,
                              void* d_out, int out_size) {
    const float* q  = (const float*)d_in[0];
    const float* k  = (const float*)d_in[1];
    const float* lt = (const float*)d_in[2];
    float* out = (float*)d_out;

    // 2 * 65536 rows, 1 warp/row, 8 warps/block
    norm_kernel<<<(2 * NROWS) / 8, 256>>>(q, k);

    cudaFuncSetAttribute(gemm_exp_kernel,
                         cudaFuncAttributeMaxDynamicSharedMemorySize, SMEM_BYTES);
    dim3 grid(16, 16, 32);  // (bn, bm, bh)
    gemm_exp_kernel<<<grid, 256, SMEM_BYTES>>>(q, k, lt, out);
}

// round 4
// speedup vs baseline: 1.2544x; 1.2482x over previous
#include <cuda_runtime.h>
#include <cstdint>

#define SEQ 2048
#define DIM 128
#define BHN 32
#define NROWS (BHN * SEQ)   // 65536 rows each for q and k

// Scratch: reciprocal L2 norms (no device allocation allowed -> __device__ globals)
__device__ float g_rq[NROWS];
__device__ float g_rk[NROWS];

// ---------------------------------------------------------------------------
// Kernel 1: per-row 1/max(||x||, 1e-12). One warp per row.
// ---------------------------------------------------------------------------
__global__ void norm_kernel(const float* __restrict__ q, const float* __restrict__ k) {
    int gwarp = (blockIdx.x * blockDim.x + threadIdx.x) >> 5;
    int lane = threadIdx.x & 31;
    bool is_q = gwarp < NROWS;
    int row = is_q ? gwarp : gwarp - NROWS;
    const float* src = is_q ? q : k;
    float4 v = reinterpret_cast<const float4*>(src + (size_t)row * DIM)[lane];
    float ss = v.x * v.x + v.y * v.y + v.z * v.z + v.w * v.w;
#pragma unroll
    for (int o = 16; o > 0; o >>= 1) ss += __shfl_xor_sync(0xffffffffu, ss, o);
    if (lane == 0) {
        float r = 1.0f / fmaxf(sqrtf(ss), 1e-12f);
        if (is_q) g_rq[row] = r; else g_rk[row] = r;
    }
}

// ---------------------------------------------------------------------------
// Helpers
// ---------------------------------------------------------------------------
__device__ __forceinline__ uint32_t smem_to_u32(const void* p) {
    uint32_t a;
    asm("{ .reg .u64 t; cvta.to.shared.u64 t, %1; cvt.u32.u64 %0, t; }" : "=r"(a) : "l"(p));
    return a;
}

#define CP_ASYNC16(dst, src) \
    asm volatile("cp.async.ca.shared.global [%0], [%1], 16;" :: "r"(dst), "l"(src))
#define CP_COMMIT() asm volatile("cp.async.commit_group;" ::: "memory")
#define CP_WAIT(n)  asm volatile("cp.async.wait_group %0;" :: "n"(n) : "memory")

__device__ __forceinline__ void ldsm_x4(unsigned r[4], uint32_t addr) {
    asm volatile("ldmatrix.sync.aligned.m8n8.x4.shared.b16 {%0,%1,%2,%3}, [%4];"
                 : "=r"(r[0]), "=r"(r[1]), "=r"(r[2]), "=r"(r[3]) : "r"(addr));
}

__device__ __forceinline__ void mma_tf32(float c[4], const unsigned a[4],
                                         unsigned b0, unsigned b1) {
    asm volatile(
        "mma.sync.aligned.m16n8k8.row.col.f32.tf32.tf32.f32 "
        "{%0,%1,%2,%3}, {%4,%5,%6,%7}, {%8,%9}, {%0,%1,%2,%3};\n"
        : "+f"(c[0]), "+f"(c[1]), "+f"(c[2]), "+f"(c[3])
        : "r"(a[0]), "r"(a[1]), "r"(a[2]), "r"(a[3]), "r"(b0), "r"(b1));
}

// ---------------------------------------------------------------------------
// Kernel 2: tile M=128 (q rows) x N=256 (k rows), K=128, 256 threads.
// cp.async staging (raw fp32 bits -> HW tf32 truncation), K split into two
// 64-deep halves for load/compute overlap. ldmatrix fragment feeding.
// smem (floats, padded rows LDA=132):
//   As[128][132] at 0        (67584 B)
//   Bs[256][132] at 67584    (135168 B)
//   rk[256]      at 202752
//   rq[128]      at 203776
// ---------------------------------------------------------------------------
#define LDA 132
#define SM_B   67584
#define SM_RK  202752
#define SM_RQ  203776
#define SMEM_TOTAL 204288

__global__ __launch_bounds__(256, 1) void tc_gemm_exp_kernel(
    const float* __restrict__ q, const float* __restrict__ k,
    const float* __restrict__ logt, float* __restrict__ out)
{
    extern __shared__ char smem[];
    uint32_t sbase = smem_to_u32(smem);

    int bh = blockIdx.z;
    int bm = blockIdx.y;   // 16 tiles of 128 q-rows
    int bn = blockIdx.x;   // 8 tiles of 256 k-rows
    int tid = threadIdx.x;
    int warp = tid >> 5, lane = tid & 31;
    int wm = warp >> 2, wn = warp & 3;       // 2 x 4 warp grid
    int wmo = wm * 64, wno = wn * 64;        // warp tile 64 x 64

    const float* qbase = q + ((size_t)bh * SEQ + (size_t)bm * 128) * DIM;
    const float* kbase = k + ((size_t)bh * SEQ + (size_t)bn * 256) * DIM;

    // ---- stage rq/rk into smem (plain stores, covered by first barrier) ----
    {
        float* srk = reinterpret_cast<float*>(smem + SM_RK);
        float* srq = reinterpret_cast<float*>(smem + SM_RQ);
        srk[tid] = g_rk[(size_t)bh * SEQ + (size_t)bn * 256 + tid];
        if (tid < 128) srq[tid] = g_rq[(size_t)bh * SEQ + (size_t)bm * 128 + tid];
    }

    // ---- cp.async staging: two K-halves, each its own commit group ----
#pragma unroll
    for (int h = 0; h < 2; h++) {
        // A half: 128 rows x 16 16B-chunks = 2048 -> 8 per thread
#pragma unroll
        for (int i = 0; i < 8; i++) {
            int id = tid + i * 256;
            int r = id >> 4, c = id & 15;
            uint32_t dst = sbase + (uint32_t)((r * LDA + h * 64 + c * 4) * 4);
            const float* src = qbase + (size_t)r * DIM + h * 64 + c * 4;
            CP_ASYNC16(dst, src);
        }
        // B half: 256 rows x 16 chunks = 4096 -> 16 per thread
#pragma unroll
        for (int i = 0; i < 16; i++) {
            int id = tid + i * 256;
            int r = id >> 4, c = id & 15;
            uint32_t dst = sbase + SM_B + (uint32_t)((r * LDA + h * 64 + c * 4) * 4);
            const float* src = kbase + (size_t)r * DIM + h * 64 + c * 4;
            CP_ASYNC16(dst, src);
        }
        CP_COMMIT();
    }

    // ---- fragment base addresses (ldmatrix row pointers) ----
    int g = lane >> 3, lr = lane & 7;
    uint32_t aAddr[4], bAddr[4];
#pragma unroll
    for (int mi = 0; mi < 4; mi++)
        aAddr[mi] = sbase +
            (uint32_t)(((wmo + mi * 16 + (g & 1) * 8 + lr) * LDA + (g >> 1) * 4) * 4);
#pragma unroll
    for (int p = 0; p < 4; p++)
        bAddr[p] = sbase + SM_B +
            (uint32_t)(((wno + p * 16 + (g >> 1) * 8 + lr) * LDA + (g & 1) * 4) * 4);

    float acc[4][8][4];
#pragma unroll
    for (int mi = 0; mi < 4; mi++)
#pragma unroll
        for (int ni = 0; ni < 8; ni++)
#pragma unroll
            for (int r = 0; r < 4; r++) acc[mi][ni][r] = 0.0f;

    // ---- compute: half 0 (overlaps half-1 loads), then half 1 ----
    CP_WAIT(1);
    __syncthreads();

#pragma unroll
    for (int s = 0; s < 8; s++) {
        uint32_t kb = (uint32_t)(s * 8 * 4);
        unsigned a[4][4], b[4][4];
#pragma unroll
        for (int mi = 0; mi < 4; mi++) ldsm_x4(a[mi], aAddr[mi] + kb);
#pragma unroll
        for (int p = 0; p < 4; p++) ldsm_x4(b[p], bAddr[p] + kb);
#pragma unroll
        for (int mi = 0; mi < 4; mi++)
#pragma unroll
            for (int p = 0; p < 4; p++) {
                mma_tf32(acc[mi][2 * p],     a[mi], b[p][0], b[p][1]);
                mma_tf32(acc[mi][2 * p + 1], a[mi], b[p][2], b[p][3]);
            }
    }

    CP_WAIT(0);
    __syncthreads();

#pragma unroll
    for (int s = 0; s < 8; s++) {
        uint32_t kb = (uint32_t)((64 + s * 8) * 4);
        unsigned a[4][4], b[4][4];
#pragma unroll
        for (int mi = 0; mi < 4; mi++) ldsm_x4(a[mi], aAddr[mi] + kb);
#pragma unroll
        for (int p = 0; p < 4; p++) ldsm_x4(b[p], bAddr[p] + kb);
#pragma unroll
        for (int mi = 0; mi < 4; mi++)
#pragma unroll
            for (int p = 0; p < 4; p++) {
                mma_tf32(acc[mi][2 * p],     a[mi], b[p][0], b[p][1]);
                mma_tf32(acc[mi][2 * p + 1], a[mi], b[p][2], b[p][3]);
            }
    }

    // ---- epilogue ----
    float lt = *logt;
    float temp = fminf(fmaxf(__expf(lt), 0.05f), 100.0f);
    float invt = 1.0f / temp;

    const float* srk = reinterpret_cast<const float*>(smem + SM_RK);
    const float* srq = reinterpret_cast<const float*>(smem + SM_RQ);
    int gid = lane >> 2, tig = lane & 3;

    float rkv[8][2];
#pragma unroll
    for (int ni = 0; ni < 8; ni++) {
        int c = wno + ni * 8 + tig * 2;
        rkv[ni][0] = srk[c] * invt;
        rkv[ni][1] = srk[c + 1] * invt;
    }

    size_t obase = (size_t)bh * SEQ * SEQ + (size_t)bn * 256;
#pragma unroll
    for (int mi = 0; mi < 4; mi++) {
        int r0 = wmo + mi * 16 + gid;
        float rq0 = srq[r0];
        float rq1 = srq[r0 + 8];
        float* o0p = out + obase + (size_t)(bm * 128 + r0) * SEQ;
        float* o1p = o0p + (size_t)8 * SEQ;
#pragma unroll
        for (int ni = 0; ni < 8; ni++) {
            int c0 = wno + ni * 8 + tig * 2;
            float s00 = fminf(fmaxf(acc[mi][ni][0] * rq0 * rkv[ni][0], -100.0f), 100.0f);
            float s01 = fminf(fmaxf(acc[mi][ni][1] * rq0 * rkv[ni][1], -100.0f), 100.0f);
            float s10 = fminf(fmaxf(acc[mi][ni][2] * rq1 * rkv[ni][0], -100.0f), 100.0f);
            float s11 = fminf(fmaxf(acc[mi][ni][3] * rq1 * rkv[ni][1], -100.0f), 100.0f);
            float2 o0, o1;
            o0.x = __expf(s00) + 1e-6f;
            o0.y = __expf(s01) + 1e-6f;
            o1.x = __expf(s10) + 1e-6f;
            o1.y = __expf(s11) + 1e-6f;
            *reinterpret_cast<float2*>(o0p + c0) = o0;
            *reinterpret_cast<float2*>(o1p + c0) = o1;
        }
    }
}

// ---------------------------------------------------------------------------
// Launcher (graph-capturable: kernel launches only)
// ---------------------------------------------------------------------------
extern "C" void kernel_launch(void* const* d_in, const int* in_sizes, int n_in,
                              void* d_out, int out_size) {
    const float* q  = (const float*)d_in[0];
    const float* k  = (const float*)d_in[1];
    const float* lt = (const float*)d_in[2];
    float* out = (float*)d_out;

    norm_kernel<<<(2 * NROWS) / 8, 256>>>(q, k);

    cudaFuncSetAttribute(tc_gemm_exp_kernel,
                         cudaFuncAttributeMaxDynamicSharedMemorySize, SMEM_TOTAL);
    dim3 grid(8, 16, 32);  // (bn, bm, bh)
    tc_gemm_exp_kernel<<<grid, 256, SMEM_TOTAL>>>(q, k, lt, out);
}